// round 6
// baseline (speedup 1.0000x reference)
#include <cuda_runtime.h>
#include <math.h>

#define NBLK 128
#define NTHR 512
typedef unsigned long long u64;

__device__ __align__(16) float g_fcT[2048 * 256];   // fc_in^T [col][r]
__device__ __align__(16) float g_xT [512 * 256];    // map out^T [j][r]
__device__ __align__(16) float g_x1T[512 * 256];    // layer0 h2 (pre-tanh) [j][r]
__device__ __align__(16) float g_hT [4 * 512 * 256];// tanh(h) [l*2+parity][j][r]
__device__ __align__(16) float g_cT [2 * 512 * 256];// tanh(c) [l][j][r]
__device__ unsigned g_cnt = 0, g_gen = 0;

#define OFF_WMAP 0        // 2048*16B map weights
#define OFF_W0   32768    // lstm0 weights
#define OFF_W1   98304    // lstm1 weights
#define OFF_BS   163840   // biases
#define OFF_STG  164096   // 64KB: per-group 16KB stage (2x8KB double buffer) / reduce spill
#define SMEMSZ   229632

__device__ __forceinline__ u64 pk2(float x){ u64 d; asm("mov.b64 %0,{%1,%1};":"=l"(d):"f"(x)); return d; }
__device__ __forceinline__ void fma2(u64& d, u64 a, u64 b){ asm("fma.rn.f32x2 %0,%1,%2,%0;":"+l"(d):"l"(a),"l"(b)); }
__device__ __forceinline__ float2 up(u64 v){ float2 r; asm("mov.b64 {%0,%1},%2;":"=f"(r.x),"=f"(r.y):"l"(v)); return r; }
__device__ __forceinline__ float sigm(float x){ return 1.f/(1.f+__expf(-x)); }
__device__ __forceinline__ void barg(int id){ asm volatile("bar.sync %0, 128;"::"r"(id):"memory"); }

// stage 8 k-rows (8KB) of A into group's buffer b; 128 threads x 4x16B
__device__ __forceinline__ void stage8(unsigned sgb, const float* __restrict__ A, int c, int b, int tp){
#pragma unroll
    for (int i = 0; i < 4; i++){
        int unit = tp*4 + i, kl = unit >> 6, r4 = (unit & 63)*4;
        asm volatile("cp.async.cg.shared.global [%0],[%1],16;"
            ::"r"(sgb + (unsigned)(b*8192 + kl*1024 + r4*4)),
              "l"(A + (size_t)(c*8 + kl)*256 + r4) : "memory");
    }
    asm volatile("cp.async.commit_group;" ::: "memory");
}
__device__ __forceinline__ void cpwait(int tail){
    if (tail) asm volatile("cp.async.wait_group 0;":::"memory");
    else      asm volatile("cp.async.wait_group 1;":::"memory");
}

__device__ __forceinline__ void gbar(){
    __syncthreads();
    if (threadIdx.x == 0){
        __threadfence();
        unsigned gen = *(volatile unsigned*)&g_gen;
        if (atomicAdd(&g_cnt, 1u) == NBLK - 1){ g_cnt = 0u; __threadfence(); atomicExch(&g_gen, gen + 1u); }
        else while (*(volatile unsigned*)&g_gen == gen) __nanosleep(32);
    }
    __syncthreads();
    __threadfence();
}

// one LSTM layer: block owns units u0..u0+3 (16 gate rows), K=1024 split 4-way, A staged via cp.async
__device__ __forceinline__ void lstm_stage(int l, int p, const float* __restrict__ xT,
    const ulonglong2* __restrict__ wS, const float* __restrict__ bs, float* S, int u0)
{
    const int t = threadIdx.x, grp = t >> 7, tp = t & 127, r0 = tp * 2;
    const int half = grp >> 1, sub = grp & 1;
    const float* A = (half ? g_hT + (size_t)(l*2+p)*512*256 : xT) + (size_t)(sub*256)*256;
    float* Sg = S + grp*4096;
    unsigned sgb = (unsigned)__cvta_generic_to_shared(Sg);
    const ulonglong2* W = wS + (size_t)(half*512 + sub*256)*4;

    u64 acc[2][8];
#pragma unroll
    for (int i = 0; i < 2; i++)
#pragma unroll
        for (int q = 0; q < 8; q++) acc[i][q] = 0ULL;

    stage8(sgb, A, 0, 0, tp);
    for (int c = 0; c < 32; c++){
        if (c < 31) stage8(sgb, A, c+1, (c+1)&1, tp);
        cpwait(c == 31);
        barg(1 + grp);
        const float* B = Sg + (c&1)*2048;
#pragma unroll
        for (int kl = 0; kl < 8; kl++){
            float2 a = *(const float2*)(B + kl*256 + r0);
            int k = c*8 + kl;
            ulonglong2 w0 = W[k*4+0], w1 = W[k*4+1], w2 = W[k*4+2], w3 = W[k*4+3];
            u64 aa = pk2(a.x);
            fma2(acc[0][0],aa,w0.x); fma2(acc[0][1],aa,w0.y); fma2(acc[0][2],aa,w1.x); fma2(acc[0][3],aa,w1.y);
            fma2(acc[0][4],aa,w2.x); fma2(acc[0][5],aa,w2.y); fma2(acc[0][6],aa,w3.x); fma2(acc[0][7],aa,w3.y);
            aa = pk2(a.y);
            fma2(acc[1][0],aa,w0.x); fma2(acc[1][1],aa,w0.y); fma2(acc[1][2],aa,w1.x); fma2(acc[1][3],aa,w1.y);
            fma2(acc[1][4],aa,w2.x); fma2(acc[1][5],aa,w2.y); fma2(acc[1][6],aa,w3.x); fma2(acc[1][7],aa,w3.y);
        }
        barg(1 + grp);
    }
    // spill into own group's stage area (safe: group done reading it)
    if (grp){
        u64* rg = (u64*)Sg;
#pragma unroll
        for (int i = 0; i < 2; i++)
#pragma unroll
            for (int q = 0; q < 8; q++) rg[tp*16 + i*8 + q] = acc[i][q];
    }
    __syncthreads();
    if (!grp){
#pragma unroll
        for (int i = 0; i < 2; i++){
            int r = r0 + i;
            float g16[16];
#pragma unroll
            for (int q = 0; q < 8; q++){
                float2 v = up(acc[i][q]);
#pragma unroll
                for (int g = 1; g < 4; g++){
                    float2 x2 = up(((const u64*)(S + g*4096))[tp*16 + i*8 + q]);
                    v.x += x2.x; v.y += x2.y;
                }
                g16[2*q] = v.x + bs[2*q]; g16[2*q+1] = v.y + bs[2*q+1];
            }
#pragma unroll
            for (int ul = 0; ul < 4; ul++){
                int u = u0 + ul;
                float gi = g16[ul], gf = g16[4+ul], gg = g16[8+ul], go = g16[12+ul];
                size_t ci = (size_t)l*512*256 + (size_t)u*256 + r;
                float c2 = sigm(gf) * g_cT[ci] + sigm(gi) * tanhf(gg);
                float h2 = sigm(go) * tanhf(c2);
                float th = tanhf(h2), tc = tanhf(c2);
                g_cT[ci] = tc;
                g_hT[(size_t)(l*2 + (p^1))*512*256 + (size_t)u*256 + r] = th;
                if (l == 0) g_x1T[(size_t)u*256 + r] = h2;
                int rr = l*128 + (r >> 1), ch = (r & 1)*1024 + u;
                g_fcT[(size_t)ch*256 + rr] = th;
                g_fcT[(size_t)(ch + 512)*256 + rr] = tc;
            }
        }
    }
}

extern "C" __global__ void __launch_bounds__(NTHR, 1)
dec_kernel(const float* __restrict__ latent, const float* __restrict__ fc_w,
    const float* __restrict__ fc_b, const float* __restrict__ map_w, const float* __restrict__ map_b,
    const float* __restrict__ wih0, const float* __restrict__ whh0, const float* __restrict__ bih0,
    const float* __restrict__ bhh0, const float* __restrict__ wih1, const float* __restrict__ whh1,
    const float* __restrict__ bih1, const float* __restrict__ bhh1, float* __restrict__ out)
{
    extern __shared__ unsigned char smem[];
    float* wmapF = (float*)(smem + OFF_WMAP);
    float* w0F   = (float*)(smem + OFF_W0);
    float* w1F   = (float*)(smem + OFF_W1);
    float* bs    = (float*)(smem + OFF_BS);
    float* S     = (float*)(smem + OFF_STG);
    const int t = threadIdx.x, blk = blockIdx.x, u0 = blk*4, j0 = blk*4;

    for (int idx = t; idx < 2048*4; idx += NTHR){
        int k = idx >> 2, jl = idx & 3;
        wmapF[idx] = map_w[(size_t)(j0 + jl)*2048 + k];
    }
    for (int idx = t; idx < 1024*16; idx += NTHR){
        int k = idx >> 4, rr = idx & 15, row = (rr >> 2)*512 + u0 + (rr & 3);
        w0F[idx] = k < 512 ? wih0[(size_t)row*512 + k] : whh0[(size_t)row*512 + k - 512];
        w1F[idx] = k < 512 ? wih1[(size_t)row*512 + k] : whh1[(size_t)row*512 + k - 512];
    }
    if (t < 16){ int row = (t >> 2)*512 + u0 + (t & 3); bs[t] = bih0[row] + bhh0[row]; bs[16 + t] = bih1[row] + bhh1[row]; }
    if (t < 4) bs[32 + t] = map_b[j0 + t];
    __syncthreads();

    // ---- init: dec = tanh(latent @ fc_w.T + fc_b) ----
    {
        float* sL = S;
        int b0 = blk*2;
        for (int idx = t; idx < 512; idx += NTHR)
            sL[idx] = latent[(size_t)(b0 + (idx >> 8))*256 + (idx & 255)];
        __syncthreads();
        int bi = t >> 8, jb = (t & 255)*8, b = b0 + bi;
        const float* la = sL + bi*256;
        for (int m = 0; m < 8; m++){
            int jj = jb + m; float s = fc_b[jj];
            const float4* wr = (const float4*)(fc_w + (size_t)jj*256);
#pragma unroll 4
            for (int k4 = 0; k4 < 64; k4++){
                float4 w = wr[k4];
                s += la[k4*4]*w.x + la[k4*4+1]*w.y + la[k4*4+2]*w.z + la[k4*4+3]*w.w;
            }
            float val = tanhf(s);
            int l = b >> 7, b2 = ((b & 127)*2 + (jj >> 10)), jj2 = jj & 1023;
            if (jj2 < 512) g_hT[(size_t)(l*2)*512*256 + (size_t)jj2*256 + b2] = val;
            else           g_cT[(size_t)l*512*256 + (size_t)(jj2 - 512)*256 + b2] = val;
            int rr = l*128 + (b2 >> 1);
            g_fcT[(size_t)((b2 & 1)*1024 + jj2)*256 + rr] = val;
        }
        __syncthreads();
    }
    gbar();

    // ================= 256 sequential steps =================
    for (int step = 0; step < 256; step++){
        int p = step & 1;
        // ---- map: 4 cols, K=2048 split 4-way, staged ----
        {
            const int grp = t >> 7, tp = t & 127, r0 = tp*2;
            const float* A = g_fcT + (size_t)(grp*512)*256;
            float* Sg = S + grp*4096;
            unsigned sgb = (unsigned)__cvta_generic_to_shared(Sg);
            const ulonglong2* W = (const ulonglong2*)wmapF + grp*512;
            u64 acc[2][2] = {{0ULL,0ULL},{0ULL,0ULL}};
            stage8(sgb, A, 0, 0, tp);
            for (int c = 0; c < 64; c++){
                if (c < 63) stage8(sgb, A, c+1, (c+1)&1, tp);
                cpwait(c == 63);
                barg(1 + grp);
                const float* B = Sg + (c&1)*2048;
#pragma unroll
                for (int kl = 0; kl < 8; kl++){
                    float2 a = *(const float2*)(B + kl*256 + r0);
                    ulonglong2 w = W[c*8 + kl];
                    u64 aa = pk2(a.x); fma2(acc[0][0],aa,w.x); fma2(acc[0][1],aa,w.y);
                    aa = pk2(a.y);     fma2(acc[1][0],aa,w.x); fma2(acc[1][1],aa,w.y);
                }
                barg(1 + grp);
            }
            if (grp){
                u64* rg = (u64*)Sg;
                rg[tp*4+0]=acc[0][0]; rg[tp*4+1]=acc[0][1]; rg[tp*4+2]=acc[1][0]; rg[tp*4+3]=acc[1][1];
            }
            __syncthreads();
            if (!grp){
#pragma unroll
                for (int i = 0; i < 2; i++){
                    int r = r0 + i;
                    float2 v0 = up(acc[i][0]), v1 = up(acc[i][1]);
#pragma unroll
                    for (int g = 1; g < 4; g++){
                        const u64* rr2 = (const u64*)(S + g*4096);
                        float2 p0 = up(rr2[tp*4 + i*2]), p1 = up(rr2[tp*4 + i*2 + 1]);
                        v0.x += p0.x; v0.y += p0.y; v1.x += p1.x; v1.y += p1.y;
                    }
                    float o0 = sigm(v0.x + bs[32]), o1 = sigm(v0.y + bs[33]);
                    float o2 = sigm(v1.x + bs[34]), o3 = sigm(v1.y + bs[35]);
                    *(float4*)(out + ((size_t)step*256 + r)*512 + j0) = make_float4(o0,o1,o2,o3);
                    g_xT[(size_t)(j0+0)*256 + r] = o0; g_xT[(size_t)(j0+1)*256 + r] = o1;
                    g_xT[(size_t)(j0+2)*256 + r] = o2; g_xT[(size_t)(j0+3)*256 + r] = o3;
                }
            }
        }
        gbar();
        lstm_stage(0, p, g_xT,  (const ulonglong2*)w0F, bs,      S, u0);
        gbar();
        lstm_stage(1, p, g_x1T, (const ulonglong2*)w1F, bs + 16, S, u0);
        gbar();
    }
}

extern "C" void kernel_launch(void* const* d_in, const int* in_sizes, int n_in,
                              void* d_out, int out_size)
{
    cudaFuncSetAttribute(dec_kernel, cudaFuncAttributeMaxDynamicSharedMemorySize, SMEMSZ);
    dec_kernel<<<NBLK, NTHR, SMEMSZ>>>(
        (const float*)d_in[0], (const float*)d_in[1], (const float*)d_in[2],
        (const float*)d_in[3], (const float*)d_in[4], (const float*)d_in[5],
        (const float*)d_in[6], (const float*)d_in[7], (const float*)d_in[8],
        (const float*)d_in[9], (const float*)d_in[10], (const float*)d_in[11],
        (const float*)d_in[12], (float*)d_out);
}

// round 7
// speedup vs baseline: 1.6453x; 1.6453x over previous
#include <cuda_runtime.h>
#include <math.h>

#define NBLK 128
#define NTHR 512
typedef unsigned long long u64;

__device__ __align__(16) float g_fcT[2048 * 256];
__device__ __align__(16) float g_xT [512 * 256];
__device__ __align__(16) float g_x1T[512 * 256];
__device__ __align__(16) float g_hT [4 * 512 * 256];
__device__ __align__(16) float g_cT [2 * 512 * 256];
__device__ unsigned g_cnt = 0, g_gen = 0;

#define OFF_WMAP 0        // 32KB map weights (4 cols row-pair packed)
#define OFF_W0   32768    // 64KB lstm0
#define OFF_W1   98304    // 64KB lstm1
#define OFF_BS   163840   // biases
#define OFF_RED  164096   // 48KB reduce scratch (u64[6144], [grp][idx][tid])
#define OFF_SG   213248   // 17408B gate tile [r][17]
#define SMEMSZ   230656

__device__ __forceinline__ u64 pk2(float x){ u64 d; asm("mov.b64 %0,{%1,%1};":"=l"(d):"f"(x)); return d; }
__device__ __forceinline__ void fma2(u64& d, u64 a, u64 b){ asm("fma.rn.f32x2 %0,%1,%2,%0;":"+l"(d):"l"(a),"l"(b)); }
__device__ __forceinline__ float2 up(u64 v){ float2 r; asm("mov.b64 {%0,%1},%2;":"=f"(r.x),"=f"(r.y):"l"(v)); return r; }
__device__ __forceinline__ float sigm(float x){ return 1.f/(1.f+__expf(-x)); }

__device__ __forceinline__ void gbar(){
    __syncthreads();
    if (threadIdx.x == 0){
        __threadfence();
        unsigned gen = *(volatile unsigned*)&g_gen;
        if (atomicAdd(&g_cnt, 1u) == NBLK - 1){ g_cnt = 0u; __threadfence(); atomicExch(&g_gen, gen + 1u); }
        else while (*(volatile unsigned*)&g_gen == gen) __nanosleep(32);
    }
    __syncthreads();
    __threadfence();
}

// one LSTM layer: block owns units u0..u0+3 (16 gate rows). Threads:
// kg=t>>7 (4-way K split), rh=(t>>6)&1 (row half: 8 rows), bg=t&63 (4 batches).
__device__ __forceinline__ void lstm_stage(int l, int p, const float* __restrict__ xT,
    const ulonglong2* __restrict__ wS, const float* __restrict__ bs, u64* red, float* sg, int u0)
{
    const int t = threadIdx.x, kg = t >> 7, tp = t & 127, rh = tp >> 6, bg = tp & 63, b0 = bg*4;
    const int half = kg >> 1, sub = kg & 1;
    const float* A = ((half ? g_hT + (size_t)(l*2+p)*131072 : xT) + (size_t)(sub*256)*256) + b0;
    const ulonglong2* W = wS + (size_t)(half*512 + sub*256)*4 + rh*2;

    u64 acc[4][4];
#pragma unroll
    for (int bi = 0; bi < 4; bi++)
#pragma unroll
        for (int j = 0; j < 4; j++) acc[bi][j] = 0ULL;

#pragma unroll 4
    for (int k = 0; k < 256; k++){
        float4 a = *(const float4*)(A + (size_t)k*256);
        ulonglong2 wA = W[(size_t)k*4], wB = W[(size_t)k*4 + 1];
        u64 aa;
        aa = pk2(a.x); fma2(acc[0][0],aa,wA.x); fma2(acc[0][1],aa,wA.y); fma2(acc[0][2],aa,wB.x); fma2(acc[0][3],aa,wB.y);
        aa = pk2(a.y); fma2(acc[1][0],aa,wA.x); fma2(acc[1][1],aa,wA.y); fma2(acc[1][2],aa,wB.x); fma2(acc[1][3],aa,wB.y);
        aa = pk2(a.z); fma2(acc[2][0],aa,wA.x); fma2(acc[2][1],aa,wA.y); fma2(acc[2][2],aa,wB.x); fma2(acc[2][3],aa,wB.y);
        aa = pk2(a.w); fma2(acc[3][0],aa,wA.x); fma2(acc[3][1],aa,wA.y); fma2(acc[3][2],aa,wB.x); fma2(acc[3][3],aa,wB.y);
    }
    if (kg){
        u64* rd = red + (size_t)(kg-1)*2048 + tp;
#pragma unroll
        for (int bi = 0; bi < 4; bi++)
#pragma unroll
            for (int j = 0; j < 4; j++) rd[(bi*4+j)*128] = acc[bi][j];
    }
    __syncthreads();
    if (!kg){
#pragma unroll
        for (int bi = 0; bi < 4; bi++){
            int r = b0 + bi;
#pragma unroll
            for (int j = 0; j < 4; j++){
                float2 v = up(acc[bi][j]);
#pragma unroll
                for (int g = 0; g < 3; g++){
                    float2 x2 = up(red[(size_t)g*2048 + (bi*4+j)*128 + tp]);
                    v.x += x2.x; v.y += x2.y;
                }
                int rr = rh*8 + 2*j;
                sg[r*17 + rr]     = v.x + bs[rr];
                sg[r*17 + rr + 1] = v.y + bs[rr + 1];
            }
        }
    }
    __syncthreads();
    if (t < 256){
        const int ul = t >> 6, bq = t & 63, r = bq*4, u = u0 + ul;
        float4 th, tc, hv;
        float* thp = &th.x; float* tcp = &tc.x; float* hvp = &hv.x;
        size_t ci = (size_t)l*131072 + (size_t)u*256 + r;
        float4 cold = *(const float4*)(g_cT + ci);
        const float* cop = &cold.x;
#pragma unroll
        for (int i = 0; i < 4; i++){
            const float* gr = sg + (r+i)*17;
            float gi = gr[ul], gf = gr[4+ul], gg = gr[8+ul], go = gr[12+ul];
            float c2 = sigm(gf)*cop[i] + sigm(gi)*tanhf(gg);
            float h2 = sigm(go)*tanhf(c2);
            hvp[i] = h2; thp[i] = tanhf(h2); tcp[i] = tanhf(c2);
        }
        *(float4*)(g_cT + ci) = tc;
        *(float4*)(g_hT + (size_t)(l*2 + (p^1))*131072 + (size_t)u*256 + r) = th;
        if (l == 0) *(float4*)(g_x1T + (size_t)u*256 + r) = hv;
#pragma unroll
        for (int i = 0; i < 4; i++){
            int rr = l*128 + ((r+i) >> 1), ch = ((r+i) & 1)*1024 + u;
            g_fcT[(size_t)ch*256 + rr] = thp[i];
            g_fcT[(size_t)(ch + 512)*256 + rr] = tcp[i];
        }
    }
}

extern "C" __global__ void __launch_bounds__(NTHR, 1)
dec_kernel(const float* __restrict__ latent, const float* __restrict__ fc_w,
    const float* __restrict__ fc_b, const float* __restrict__ map_w, const float* __restrict__ map_b,
    const float* __restrict__ wih0, const float* __restrict__ whh0, const float* __restrict__ bih0,
    const float* __restrict__ bhh0, const float* __restrict__ wih1, const float* __restrict__ whh1,
    const float* __restrict__ bih1, const float* __restrict__ bhh1, float* __restrict__ out)
{
    extern __shared__ unsigned char smem[];
    float* wmapF = (float*)(smem + OFF_WMAP);
    float* w0F   = (float*)(smem + OFF_W0);
    float* w1F   = (float*)(smem + OFF_W1);
    float* bs    = (float*)(smem + OFF_BS);
    u64*   red   = (u64*)  (smem + OFF_RED);
    float* sg    = (float*)(smem + OFF_SG);
    const int t = threadIdx.x, blk = blockIdx.x, u0 = blk*4, j0 = blk*4;

    for (int idx = t; idx < 2048*4; idx += NTHR){
        int k = idx >> 2, jl = idx & 3;
        wmapF[idx] = map_w[(size_t)(j0 + jl)*2048 + k];
    }
    for (int idx = t; idx < 1024*16; idx += NTHR){
        int k = idx >> 4, rr = idx & 15, row = (rr >> 2)*512 + u0 + (rr & 3);
        w0F[idx] = k < 512 ? wih0[(size_t)row*512 + k] : whh0[(size_t)row*512 + k - 512];
        w1F[idx] = k < 512 ? wih1[(size_t)row*512 + k] : whh1[(size_t)row*512 + k - 512];
    }
    if (t < 16){ int row = (t >> 2)*512 + u0 + (t & 3); bs[t] = bih0[row] + bhh0[row]; bs[16 + t] = bih1[row] + bhh1[row]; }
    if (t < 4) bs[32 + t] = map_b[j0 + t];
    __syncthreads();

    // ---- init: dec = tanh(latent @ fc_w.T + fc_b) ----
    {
        float* sL = (float*)red;
        int b0 = blk*2;
        for (int idx = t; idx < 512; idx += NTHR)
            sL[idx] = latent[(size_t)(b0 + (idx >> 8))*256 + (idx & 255)];
        __syncthreads();
        int bi = t >> 8, jb = (t & 255)*8, b = b0 + bi;
        const float* la = sL + bi*256;
        for (int m = 0; m < 8; m++){
            int jj = jb + m; float s = fc_b[jj];
            const float4* wr = (const float4*)(fc_w + (size_t)jj*256);
#pragma unroll 4
            for (int k4 = 0; k4 < 64; k4++){
                float4 w = wr[k4];
                s += la[k4*4]*w.x + la[k4*4+1]*w.y + la[k4*4+2]*w.z + la[k4*4+3]*w.w;
            }
            float val = tanhf(s);
            int l = b >> 7, b2 = ((b & 127)*2 + (jj >> 10)), jj2 = jj & 1023;
            if (jj2 < 512) g_hT[(size_t)(l*2)*131072 + (size_t)jj2*256 + b2] = val;
            else           g_cT[(size_t)l*131072 + (size_t)(jj2 - 512)*256 + b2] = val;
            int rr = l*128 + (b2 >> 1);
            g_fcT[(size_t)((b2 & 1)*1024 + jj2)*256 + rr] = val;
        }
        __syncthreads();
    }
    gbar();

    // ================= 256 sequential steps =================
    for (int step = 0; step < 256; step++){
        int p = step & 1;
        // ---- map: 4 cols, K=2048 split 8-way; threads: kg=t>>6, bg=t&63 (4 batches) ----
        {
            const int kg = t >> 6, bg = t & 63, b0 = bg*4;
            u64 acc[4][2];
#pragma unroll
            for (int bi = 0; bi < 4; bi++){ acc[bi][0] = 0ULL; acc[bi][1] = 0ULL; }
            const float* A = g_fcT + (size_t)(kg*256)*256 + b0;
            const ulonglong2* W = (const ulonglong2*)wmapF + kg*256;
#pragma unroll 4
            for (int k = 0; k < 256; k++){
                float4 a = *(const float4*)(A + (size_t)k*256);
                ulonglong2 w = W[k];
                u64 aa;
                aa = pk2(a.x); fma2(acc[0][0],aa,w.x); fma2(acc[0][1],aa,w.y);
                aa = pk2(a.y); fma2(acc[1][0],aa,w.x); fma2(acc[1][1],aa,w.y);
                aa = pk2(a.z); fma2(acc[2][0],aa,w.x); fma2(acc[2][1],aa,w.y);
                aa = pk2(a.w); fma2(acc[3][0],aa,w.x); fma2(acc[3][1],aa,w.y);
            }
            if (kg){
                u64* rd = red + (size_t)(kg-1)*512 + bg;
#pragma unroll
                for (int bi = 0; bi < 4; bi++){ rd[(bi*2)*64] = acc[bi][0]; rd[(bi*2+1)*64] = acc[bi][1]; }
            }
            __syncthreads();
            if (!kg){
                float o[4][4];
#pragma unroll
                for (int bi = 0; bi < 4; bi++){
                    float2 v0 = up(acc[bi][0]), v1 = up(acc[bi][1]);
#pragma unroll
                    for (int g = 0; g < 7; g++){
                        float2 p0 = up(red[(size_t)g*512 + (bi*2)*64 + bg]);
                        float2 p1 = up(red[(size_t)g*512 + (bi*2+1)*64 + bg]);
                        v0.x += p0.x; v0.y += p0.y; v1.x += p1.x; v1.y += p1.y;
                    }
                    o[bi][0] = sigm(v0.x + bs[32]); o[bi][1] = sigm(v0.y + bs[33]);
                    o[bi][2] = sigm(v1.x + bs[34]); o[bi][3] = sigm(v1.y + bs[35]);
                    *(float4*)(out + ((size_t)step*256 + b0 + bi)*512 + j0) =
                        make_float4(o[bi][0], o[bi][1], o[bi][2], o[bi][3]);
                }
#pragma unroll
                for (int c = 0; c < 4; c++)
                    *(float4*)(g_xT + (size_t)(j0 + c)*256 + b0) =
                        make_float4(o[0][c], o[1][c], o[2][c], o[3][c]);
            }
        }
        gbar();
        lstm_stage(0, p, g_xT,  (const ulonglong2*)w0F, bs,      red, sg, u0);
        gbar();
        lstm_stage(1, p, g_x1T, (const ulonglong2*)w1F, bs + 16, red, sg, u0);
        gbar();
    }
}

extern "C" void kernel_launch(void* const* d_in, const int* in_sizes, int n_in,
                              void* d_out, int out_size)
{
    cudaFuncSetAttribute(dec_kernel, cudaFuncAttributeMaxDynamicSharedMemorySize, SMEMSZ);
    dec_kernel<<<NBLK, NTHR, SMEMSZ>>>(
        (const float*)d_in[0], (const float*)d_in[1], (const float*)d_in[2],
        (const float*)d_in[3], (const float*)d_in[4], (const float*)d_in[5],
        (const float*)d_in[6], (const float*)d_in[7], (const float*)d_in[8],
        (const float*)d_in[9], (const float*)d_in[10], (const float*)d_in[11],
        (const float*)d_in[12], (float*)d_out);
}